// round 1
// baseline (speedup 1.0000x reference)
#include <cuda_runtime.h>

#define NB 4
#define C 128
#define HW 4096
#define EPSF 1e-7f

#define BM 128
#define BN 128
#define BK 16

// Scratch (static __device__ arrays per harness rules)
__device__ float g_k[NB][HW][C];     // normalized k[b][l][c]   (8 MB)
__device__ float g_y[NB][C][HW];     // 3x3 box-summed x        (8 MB)
__device__ float g_S[NB][HW][HW];    // scores [b][l][p]        (256 MB)
__device__ float g_cmax[NB][HW];     // per-column max
__device__ float g_crcp[NB][HW];     // per-column 1/sum

// ---------------------------------------------------------------------------
// Kernel 1: k = (x + eps) row-normalized.  One block per (b, l), 128 threads.
// ---------------------------------------------------------------------------
__global__ void k_prep(const float* __restrict__ fg) {
    int l = blockIdx.x;
    int b = blockIdx.y;
    int c = threadIdx.x;
    float v = fg[((b * C + c) * HW) + l] + EPSF;
    float s = v * v;
    #pragma unroll
    for (int o = 16; o > 0; o >>= 1) s += __shfl_xor_sync(0xffffffffu, s, o);
    __shared__ float ws[4];
    if ((c & 31) == 0) ws[c >> 5] = s;
    __syncthreads();
    float tot = ws[0] + ws[1] + ws[2] + ws[3];
    g_k[b][l][c] = v * rsqrtf(tot);
}

// ---------------------------------------------------------------------------
// Kernel 2: y = 3x3 zero-padded box sum of x.
// ---------------------------------------------------------------------------
__global__ void y_prep(const float* __restrict__ fg) {
    int idx = blockIdx.x * blockDim.x + threadIdx.x;   // over NB*C*HW
    int p   = idx & (HW - 1);
    int bc  = idx >> 12;
    int i = p >> 6, j = p & 63;
    const float* base = fg + (size_t)bc * HW;
    float s = 0.f;
    #pragma unroll
    for (int di = -1; di <= 1; di++) {
        int ii = i + di;
        if (ii < 0 || ii >= 64) continue;
        #pragma unroll
        for (int dj = -1; dj <= 1; dj++) {
            int jj = j + dj;
            if (jj < 0 || jj >= 64) continue;
            s += base[ii * 64 + jj];
        }
    }
    ((float*)g_y)[idx] = s;
}

// ---------------------------------------------------------------------------
// Kernel 3: S[b] = K[b] (4096x128) @ Y[b] (128x4096).  128x128 tile, 8x8/thr.
// ---------------------------------------------------------------------------
__global__ __launch_bounds__(256) void gemm1() {
    int b  = blockIdx.z;
    int l0 = blockIdx.y * BM;
    int p0 = blockIdx.x * BN;
    __shared__ float As[BK][BM];   // [c][l]  (transposed)
    __shared__ float Bs[BK][BN];   // [c][p]
    int tid = threadIdx.x;
    int tx = tid & 15, ty = tid >> 4;
    float acc[8][8] = {};

    const float* Ag = &g_k[b][l0][0];   // row stride C
    const float* Bg = &g_y[b][0][p0];   // row stride HW

    for (int c0 = 0; c0 < C; c0 += BK) {
        #pragma unroll
        for (int k = 0; k < 2; k++) {
            int f = tid * 2 + k;                 // 0..511
            int row = f >> 2;                    // l-local 0..127
            int c4  = (f & 3) * 4;               // c-local
            float4 v = *(const float4*)(Ag + row * C + c0 + c4);
            As[c4 + 0][row] = v.x; As[c4 + 1][row] = v.y;
            As[c4 + 2][row] = v.z; As[c4 + 3][row] = v.w;
        }
        #pragma unroll
        for (int k = 0; k < 2; k++) {
            int f = tid * 2 + k;
            int row = f >> 5;                    // c-local 0..15
            int p4  = (f & 31) * 4;              // p-local
            *(float4*)&Bs[row][p4] = *(const float4*)(Bg + (c0 + row) * HW + p4);
        }
        __syncthreads();
        #pragma unroll
        for (int kk = 0; kk < BK; kk++) {
            float a[8], bb[8];
            *(float4*)&a[0]  = *(const float4*)&As[kk][ty * 8];
            *(float4*)&a[4]  = *(const float4*)&As[kk][ty * 8 + 4];
            *(float4*)&bb[0] = *(const float4*)&Bs[kk][tx * 8];
            *(float4*)&bb[4] = *(const float4*)&Bs[kk][tx * 8 + 4];
            #pragma unroll
            for (int i = 0; i < 8; i++)
                #pragma unroll
                for (int j = 0; j < 8; j++)
                    acc[i][j] += a[i] * bb[j];
        }
        __syncthreads();
    }
    #pragma unroll
    for (int i = 0; i < 8; i++) {
        float* row = &g_S[b][l0 + ty * 8 + i][p0 + tx * 8];
        *(float4*)(row)     = make_float4(acc[i][0], acc[i][1], acc[i][2], acc[i][3]);
        *(float4*)(row + 4) = make_float4(acc[i][4], acc[i][5], acc[i][6], acc[i][7]);
    }
}

// ---------------------------------------------------------------------------
// Kernel 4: per-column (over l) max and 1/sum(exp).  One thread per column.
// ---------------------------------------------------------------------------
__global__ void softmax_stats() {
    int idx = blockIdx.x * blockDim.x + threadIdx.x;   // over NB*HW
    int b = idx >> 12;
    int p = idx & (HW - 1);
    const float* col = &g_S[b][0][0] + p;
    float m0 = -1e30f, m1 = -1e30f, m2 = -1e30f, m3 = -1e30f;
    for (int l = 0; l < HW; l += 4) {
        m0 = fmaxf(m0, col[(size_t)(l + 0) * HW]);
        m1 = fmaxf(m1, col[(size_t)(l + 1) * HW]);
        m2 = fmaxf(m2, col[(size_t)(l + 2) * HW]);
        m3 = fmaxf(m3, col[(size_t)(l + 3) * HW]);
    }
    float m = fmaxf(fmaxf(m0, m1), fmaxf(m2, m3));
    float s0 = 0.f, s1 = 0.f, s2 = 0.f, s3 = 0.f;
    for (int l = 0; l < HW; l += 4) {
        s0 += __expf(col[(size_t)(l + 0) * HW] - m);
        s1 += __expf(col[(size_t)(l + 1) * HW] - m);
        s2 += __expf(col[(size_t)(l + 2) * HW] - m);
        s3 += __expf(col[(size_t)(l + 3) * HW] - m);
    }
    g_cmax[b][p] = m;
    g_crcp[b][p] = 1.f / ((s0 + s1) + (s2 + s3));
}

// ---------------------------------------------------------------------------
// Kernel 5: R = K^T (128x4096) @ softmax(S) (4096x4096) with exp fused into
// the B-tile load, plus the output epilogue.
// ---------------------------------------------------------------------------
__global__ __launch_bounds__(256) void gemm2(const float* __restrict__ fg,
                                             const float* __restrict__ mask,
                                             float* __restrict__ out) {
    int b  = blockIdx.z;
    int p0 = blockIdx.x * BN;
    __shared__ float As[BK][BM];     // [l][c]
    __shared__ float Bs[BK][BN];     // [l][p], exp-normalized
    __shared__ float sm[BN], sr[BN], smk[BN];
    int tid = threadIdx.x;
    int tx = tid & 15, ty = tid >> 4;
    if (tid < BN) {
        sm[tid]  = g_cmax[b][p0 + tid];
        sr[tid]  = g_crcp[b][p0 + tid];
        smk[tid] = mask[b * HW + p0 + tid];
    }
    __syncthreads();
    float acc[8][8] = {};

    for (int l0 = 0; l0 < HW; l0 += BK) {
        #pragma unroll
        for (int k = 0; k < 2; k++) {
            int f = tid * 2 + k;
            int row = f >> 5;                    // l-local 0..15
            int c4  = (f & 31) * 4;              // c
            *(float4*)&As[row][c4] = *(const float4*)&g_k[b][l0 + row][c4];
        }
        #pragma unroll
        for (int k = 0; k < 2; k++) {
            int f = tid * 2 + k;
            int row = f >> 5;                    // l-local
            int p4  = (f & 31) * 4;              // p-local
            float4 v = *(const float4*)&g_S[b][l0 + row][p0 + p4];
            v.x = __expf(v.x - sm[p4 + 0]) * sr[p4 + 0];
            v.y = __expf(v.y - sm[p4 + 1]) * sr[p4 + 1];
            v.z = __expf(v.z - sm[p4 + 2]) * sr[p4 + 2];
            v.w = __expf(v.w - sm[p4 + 3]) * sr[p4 + 3];
            *(float4*)&Bs[row][p4] = v;
        }
        __syncthreads();
        #pragma unroll
        for (int kk = 0; kk < BK; kk++) {
            float a[8], bb[8];
            *(float4*)&a[0]  = *(const float4*)&As[kk][ty * 8];
            *(float4*)&a[4]  = *(const float4*)&As[kk][ty * 8 + 4];
            *(float4*)&bb[0] = *(const float4*)&Bs[kk][tx * 8];
            *(float4*)&bb[4] = *(const float4*)&Bs[kk][tx * 8 + 4];
            #pragma unroll
            for (int i = 0; i < 8; i++)
                #pragma unroll
                for (int j = 0; j < 8; j++)
                    acc[i][j] += a[i] * bb[j];
        }
        __syncthreads();
    }
    // epilogue: out = R*(1-m)/9 + x*m
    #pragma unroll
    for (int i = 0; i < 8; i++) {
        int c = ty * 8 + i;
        const float* frow = fg  + ((size_t)(b * C + c)) * HW + p0;
        float*       orow = out + ((size_t)(b * C + c)) * HW + p0;
        #pragma unroll
        for (int j = 0; j < 8; j++) {
            int pl = tx * 8 + j;
            float mk = smk[pl];
            orow[pl] = acc[i][j] * (1.f - mk) * (1.f / 9.f) + frow[pl] * mk;
        }
    }
}

extern "C" void kernel_launch(void* const* d_in, const int* in_sizes, int n_in,
                              void* d_out, int out_size) {
    const float* fg   = (const float*)d_in[0];
    const float* mask = (const float*)d_in[1];
    float* out = (float*)d_out;

    k_prep<<<dim3(HW, NB), C>>>(fg);
    y_prep<<<(NB * C * HW) / 256, 256>>>(fg);
    gemm1<<<dim3(HW / BN, HW / BM, NB), 256>>>();
    softmax_stats<<<(NB * HW) / 256, 256>>>();
    gemm2<<<dim3(HW / BN, 1, NB), 256>>>(fg, mask, out);
}

// round 2
// speedup vs baseline: 1.3007x; 1.3007x over previous
#include <cuda_runtime.h>

#define NB 4
#define C 128
#define HW 4096
#define EPSF 1e-7f

#define BM 128
#define BN 128
#define BK 16
#define NTILES (HW / BM)   // 32 row tiles in gemm1

// Scratch (static __device__ arrays per harness rules)
__device__ float g_k[NB][HW][C];      // normalized k[b][l][c]   (8 MB)
__device__ float g_y[NB][C][HW];      // 3x3 box-summed x        (8 MB)
__device__ float g_S[NB][HW][HW];     // scores [b][l][p]        (256 MB)
__device__ float g_pm[NTILES][NB][HW]; // partial col max per row-tile (2 MB)
__device__ float g_ps[NTILES][NB][HW]; // partial col expsum per row-tile
__device__ float g_cmax[NB][HW];      // per-column max
__device__ float g_crcp[NB][HW];      // per-column 1/sum

// ---------------------------------------------------------------------------
// Kernel 1: k = (x + eps) row-normalized.  One block per (b, l), 128 threads.
// ---------------------------------------------------------------------------
__global__ void k_prep(const float* __restrict__ fg) {
    int l = blockIdx.x;
    int b = blockIdx.y;
    int c = threadIdx.x;
    float v = fg[((b * C + c) * HW) + l] + EPSF;
    float s = v * v;
    #pragma unroll
    for (int o = 16; o > 0; o >>= 1) s += __shfl_xor_sync(0xffffffffu, s, o);
    __shared__ float ws[4];
    if ((c & 31) == 0) ws[c >> 5] = s;
    __syncthreads();
    float tot = ws[0] + ws[1] + ws[2] + ws[3];
    g_k[b][l][c] = v * rsqrtf(tot);
}

// ---------------------------------------------------------------------------
// Kernel 2: y = 3x3 zero-padded box sum of x.
// ---------------------------------------------------------------------------
__global__ void y_prep(const float* __restrict__ fg) {
    int idx = blockIdx.x * blockDim.x + threadIdx.x;   // over NB*C*HW
    int p   = idx & (HW - 1);
    int bc  = idx >> 12;
    int i = p >> 6, j = p & 63;
    const float* base = fg + (size_t)bc * HW;
    float s = 0.f;
    #pragma unroll
    for (int di = -1; di <= 1; di++) {
        int ii = i + di;
        if (ii < 0 || ii >= 64) continue;
        #pragma unroll
        for (int dj = -1; dj <= 1; dj++) {
            int jj = j + dj;
            if (jj < 0 || jj >= 64) continue;
            s += base[ii * 64 + jj];
        }
    }
    ((float*)g_y)[idx] = s;
}

// ---------------------------------------------------------------------------
// Kernel 3: S[b] = K[b] (4096x128) @ Y[b] (128x4096).  128x128 tile, 8x8/thr.
// Epilogue also emits per-(row-tile, column) partial softmax stats.
// ---------------------------------------------------------------------------
__global__ __launch_bounds__(256) void gemm1() {
    int b  = blockIdx.z;
    int lt = blockIdx.y;
    int l0 = lt * BM;
    int p0 = blockIdx.x * BN;
    __shared__ float As[BK][BM];   // [c][l]  (transposed)
    __shared__ float Bs[BK][BN];   // [c][p]
    int tid = threadIdx.x;
    int tx = tid & 15, ty = tid >> 4;
    float acc[8][8] = {};

    const float* Ag = &g_k[b][l0][0];   // row stride C
    const float* Bg = &g_y[b][0][p0];   // row stride HW

    for (int c0 = 0; c0 < C; c0 += BK) {
        #pragma unroll
        for (int k = 0; k < 2; k++) {
            int f = tid * 2 + k;                 // 0..511
            int row = f >> 2;                    // l-local 0..127
            int c4  = (f & 3) * 4;               // c-local
            float4 v = *(const float4*)(Ag + row * C + c0 + c4);
            As[c4 + 0][row] = v.x; As[c4 + 1][row] = v.y;
            As[c4 + 2][row] = v.z; As[c4 + 3][row] = v.w;
        }
        #pragma unroll
        for (int k = 0; k < 2; k++) {
            int f = tid * 2 + k;
            int row = f >> 5;                    // c-local 0..15
            int p4  = (f & 31) * 4;              // p-local
            *(float4*)&Bs[row][p4] = *(const float4*)(Bg + (c0 + row) * HW + p4);
        }
        __syncthreads();
        #pragma unroll
        for (int kk = 0; kk < BK; kk++) {
            float a[8], bb[8];
            *(float4*)&a[0]  = *(const float4*)&As[kk][ty * 8];
            *(float4*)&a[4]  = *(const float4*)&As[kk][ty * 8 + 4];
            *(float4*)&bb[0] = *(const float4*)&Bs[kk][tx * 8];
            *(float4*)&bb[4] = *(const float4*)&Bs[kk][tx * 8 + 4];
            #pragma unroll
            for (int i = 0; i < 8; i++)
                #pragma unroll
                for (int j = 0; j < 8; j++)
                    acc[i][j] += a[i] * bb[j];
        }
        __syncthreads();
    }
    // write S tile
    #pragma unroll
    for (int i = 0; i < 8; i++) {
        float* row = &g_S[b][l0 + ty * 8 + i][p0 + tx * 8];
        *(float4*)(row)     = make_float4(acc[i][0], acc[i][1], acc[i][2], acc[i][3]);
        *(float4*)(row + 4) = make_float4(acc[i][4], acc[i][5], acc[i][6], acc[i][7]);
    }

    // partial softmax stats for this 128-row tile: per column max + expsum
    __shared__ float pm[16][BN];
    __shared__ float ps[16][BN];
    #pragma unroll
    for (int j = 0; j < 8; j++) {
        float m = acc[0][j];
        #pragma unroll
        for (int i = 1; i < 8; i++) m = fmaxf(m, acc[i][j]);
        float s = 0.f;
        #pragma unroll
        for (int i = 0; i < 8; i++) s += __expf(acc[i][j] - m);
        pm[ty][tx * 8 + j] = m;
        ps[ty][tx * 8 + j] = s;
    }
    __syncthreads();
    if (tid < BN) {
        float m = pm[0][tid];
        #pragma unroll
        for (int t = 1; t < 16; t++) m = fmaxf(m, pm[t][tid]);
        float s = 0.f;
        #pragma unroll
        for (int t = 0; t < 16; t++) s += ps[t][tid] * __expf(pm[t][tid] - m);
        g_pm[lt][b][p0 + tid] = m;
        g_ps[lt][b][p0 + tid] = s;
    }
}

// ---------------------------------------------------------------------------
// Kernel 4: combine the 32 per-tile partials per column (online softmax).
// ---------------------------------------------------------------------------
__global__ void softmax_combine() {
    int idx = blockIdx.x * blockDim.x + threadIdx.x;   // over NB*HW
    int b = idx >> 12;
    int p = idx & (HW - 1);
    float m = g_pm[0][b][p];
    float s = g_ps[0][b][p];
    #pragma unroll
    for (int t = 1; t < NTILES; t++) {
        float mt = g_pm[t][b][p];
        float st = g_ps[t][b][p];
        float mn = fmaxf(m, mt);
        s = s * __expf(m - mn) + st * __expf(mt - mn);
        m = mn;
    }
    g_cmax[b][p] = m;
    g_crcp[b][p] = 1.f / s;
}

// ---------------------------------------------------------------------------
// Kernel 5: R = K^T (128x4096) @ softmax(S) (4096x4096) with exp fused into
// the B-tile load, plus the output epilogue.
// ---------------------------------------------------------------------------
__global__ __launch_bounds__(256) void gemm2(const float* __restrict__ fg,
                                             const float* __restrict__ mask,
                                             float* __restrict__ out) {
    int b  = blockIdx.z;
    int p0 = blockIdx.x * BN;
    __shared__ float As[BK][BM];     // [l][c]
    __shared__ float Bs[BK][BN];     // [l][p], exp-normalized
    __shared__ float sm[BN], sr[BN], smk[BN];
    int tid = threadIdx.x;
    int tx = tid & 15, ty = tid >> 4;
    if (tid < BN) {
        sm[tid]  = g_cmax[b][p0 + tid];
        sr[tid]  = g_crcp[b][p0 + tid];
        smk[tid] = mask[b * HW + p0 + tid];
    }
    __syncthreads();
    float acc[8][8] = {};

    for (int l0 = 0; l0 < HW; l0 += BK) {
        #pragma unroll
        for (int k = 0; k < 2; k++) {
            int f = tid * 2 + k;
            int row = f >> 5;                    // l-local 0..15
            int c4  = (f & 31) * 4;              // c
            *(float4*)&As[row][c4] = *(const float4*)&g_k[b][l0 + row][c4];
        }
        #pragma unroll
        for (int k = 0; k < 2; k++) {
            int f = tid * 2 + k;
            int row = f >> 5;                    // l-local
            int p4  = (f & 31) * 4;              // p-local
            float4 v = *(const float4*)&g_S[b][l0 + row][p0 + p4];
            v.x = __expf(v.x - sm[p4 + 0]) * sr[p4 + 0];
            v.y = __expf(v.y - sm[p4 + 1]) * sr[p4 + 1];
            v.z = __expf(v.z - sm[p4 + 2]) * sr[p4 + 2];
            v.w = __expf(v.w - sm[p4 + 3]) * sr[p4 + 3];
            *(float4*)&Bs[row][p4] = v;
        }
        __syncthreads();
        #pragma unroll
        for (int kk = 0; kk < BK; kk++) {
            float a[8], bb[8];
            *(float4*)&a[0]  = *(const float4*)&As[kk][ty * 8];
            *(float4*)&a[4]  = *(const float4*)&As[kk][ty * 8 + 4];
            *(float4*)&bb[0] = *(const float4*)&Bs[kk][tx * 8];
            *(float4*)&bb[4] = *(const float4*)&Bs[kk][tx * 8 + 4];
            #pragma unroll
            for (int i = 0; i < 8; i++)
                #pragma unroll
                for (int j = 0; j < 8; j++)
                    acc[i][j] += a[i] * bb[j];
        }
        __syncthreads();
    }
    // epilogue: out = R*(1-m)/9 + x*m
    #pragma unroll
    for (int i = 0; i < 8; i++) {
        int c = ty * 8 + i;
        const float* frow = fg  + ((size_t)(b * C + c)) * HW + p0;
        float*       orow = out + ((size_t)(b * C + c)) * HW + p0;
        #pragma unroll
        for (int j = 0; j < 8; j++) {
            int pl = tx * 8 + j;
            float mk = smk[pl];
            orow[pl] = acc[i][j] * (1.f - mk) * (1.f / 9.f) + frow[pl] * mk;
        }
    }
}

extern "C" void kernel_launch(void* const* d_in, const int* in_sizes, int n_in,
                              void* d_out, int out_size) {
    const float* fg   = (const float*)d_in[0];
    const float* mask = (const float*)d_in[1];
    float* out = (float*)d_out;

    k_prep<<<dim3(HW, NB), C>>>(fg);
    y_prep<<<(NB * C * HW) / 256, 256>>>(fg);
    gemm1<<<dim3(HW / BN, HW / BM, NB), 256>>>();
    softmax_combine<<<(NB * HW) / 256, 256>>>();
    gemm2<<<dim3(HW / BN, 1, NB), 256>>>(fg, mask, out);
}

// round 8
// speedup vs baseline: 1.3216x; 1.0161x over previous
#include <cuda_runtime.h>
#include <cstdint>

#define NB 4
#define C 128
#define HW 4096
#define EPSF 1e-7f
#define NTILES (HW / 128)
#define SMS 136   // padded shared stride (floats)

#define BM 128
#define BN 128
#define BK 16

// ---------------- scratch ----------------
__device__ __align__(128) float g_k [NB][HW][C];    // K[l][c]
__device__ __align__(128) float g_y [NB][C][HW];    // boxsum [c][p]
__device__ __align__(128) float g_S [NB][HW][HW];   // S[l][p]
__device__ float g_pm[NTILES][NB][HW];
__device__ float g_ps[NTILES][NB][HW];
__device__ float g_cmax[NB][HW];
__device__ float g_crcp[NB][HW];

// ---------------- helpers ----------------
__device__ __forceinline__ uint32_t f2tf(float f) {
    uint32_t u;
    asm("cvt.rna.tf32.f32 %0, %1;" : "=r"(u) : "f"(f));
    return u;
}
// split v into hi (tf32) + lo (tf32 of residual)
__device__ __forceinline__ void tf_split(float v, uint32_t& h, uint32_t& l) {
    h = f2tf(v);
    l = f2tf(v - __uint_as_float(h));
}
__device__ __forceinline__ void mma8(float* c, const uint32_t* a, const uint32_t* b) {
    asm volatile("mma.sync.aligned.m16n8k8.row.col.f32.tf32.tf32.f32 "
        "{%0,%1,%2,%3},{%4,%5,%6,%7},{%8,%9},{%0,%1,%2,%3};"
        : "+f"(c[0]), "+f"(c[1]), "+f"(c[2]), "+f"(c[3])
        : "r"(a[0]), "r"(a[1]), "r"(a[2]), "r"(a[3]), "r"(b[0]), "r"(b[1]));
}

// ---------------------------------------------------------------------------
// prep (proven)
// ---------------------------------------------------------------------------
__global__ void k_prep(const float* __restrict__ fg) {
    int l = blockIdx.x, b = blockIdx.y, c = threadIdx.x;
    float v = fg[((b * C + c) * HW) + l] + EPSF;
    float s = v * v;
    #pragma unroll
    for (int o = 16; o > 0; o >>= 1) s += __shfl_xor_sync(0xffffffffu, s, o);
    __shared__ float ws[4];
    if ((c & 31) == 0) ws[c >> 5] = s;
    __syncthreads();
    float tot = ws[0] + ws[1] + ws[2] + ws[3];
    g_k[b][l][c] = v * rsqrtf(tot);
}

__global__ void y_prep(const float* __restrict__ fg) {
    int idx = blockIdx.x * blockDim.x + threadIdx.x;
    int p = idx & (HW - 1);
    int bc = idx >> 12;
    int i = p >> 6, j = p & 63;
    const float* base = fg + (size_t)bc * HW;
    float s = 0.f;
    #pragma unroll
    for (int di = -1; di <= 1; di++) {
        int ii = i + di;
        if (ii < 0 || ii >= 64) continue;
        #pragma unroll
        for (int dj = -1; dj <= 1; dj++) {
            int jj = j + dj;
            if (jj < 0 || jj >= 64) continue;
            s += base[ii * 64 + jj];
        }
    }
    ((float*)g_y)[idx] = s;
}

// ---------------------------------------------------------------------------
// gemm1 (3xTF32 mma): S[l][p] = K[l][:] . Y[:,p]  + partial softmax stats
// block 256 = 8 warps (2m x 4n), warp tile 64x32, BK=16
// ---------------------------------------------------------------------------
__global__ __launch_bounds__(256) void gemm1_mma() {
    __shared__ uint32_t Ah[16 * SMS], Al[16 * SMS];   // [k][m]
    __shared__ uint32_t Bh[16 * SMS], Bl[16 * SMS];   // [k][n]
    __shared__ float pm_sh[2][128], ps_sh[2][128];

    int b = blockIdx.z, lt = blockIdx.y;
    int l0 = lt * 128, p0 = blockIdx.x * 128;
    int tid = threadIdx.x, wid = tid >> 5, lane = tid & 31;
    int gid = lane >> 2, tig = lane & 3;
    int wm = (wid & 1) * 64, wn = (wid >> 1) * 32;

    float acc[4][4][4] = {};
    const float* Ag = &g_k[b][l0][0];
    const float* Bg = &g_y[b][0][p0];

    int am = tid & 127, ak = (tid >> 7) * 8;   // A loader: row am, k [ak, ak+8)
    int bk = tid >> 4,  bn = (tid & 15) * 8;   // B loader: k row bk, n [bn, bn+8)

    for (int c0 = 0; c0 < C; c0 += 16) {
        #pragma unroll
        for (int i = 0; i < 2; i++) {
            float4 v = *(const float4*)(Ag + am * C + c0 + ak + i * 4);
            int k = ak + i * 4;
            uint32_t h, l;
            tf_split(v.x, h, l); Ah[(k + 0) * SMS + am] = h; Al[(k + 0) * SMS + am] = l;
            tf_split(v.y, h, l); Ah[(k + 1) * SMS + am] = h; Al[(k + 1) * SMS + am] = l;
            tf_split(v.z, h, l); Ah[(k + 2) * SMS + am] = h; Al[(k + 2) * SMS + am] = l;
            tf_split(v.w, h, l); Ah[(k + 3) * SMS + am] = h; Al[(k + 3) * SMS + am] = l;
        }
        #pragma unroll
        for (int i = 0; i < 2; i++) {
            float4 v = *(const float4*)(Bg + (size_t)(c0 + bk) * HW + bn + i * 4);
            uint4 uh, ul;
            tf_split(v.x, uh.x, ul.x);
            tf_split(v.y, uh.y, ul.y);
            tf_split(v.z, uh.z, ul.z);
            tf_split(v.w, uh.w, ul.w);
            *(uint4*)&Bh[bk * SMS + bn + i * 4] = uh;
            *(uint4*)&Bl[bk * SMS + bn + i * 4] = ul;
        }
        __syncthreads();
        #pragma unroll
        for (int kk = 0; kk < 16; kk += 8) {
            uint32_t ah[4][4], al[4][4], bh[4][2], bl[4][2];
            #pragma unroll
            for (int mf = 0; mf < 4; mf++) {
                int m = wm + mf * 16 + gid;
                ah[mf][0] = Ah[(kk + tig) * SMS + m];
                ah[mf][1] = Ah[(kk + tig) * SMS + m + 8];
                ah[mf][2] = Ah[(kk + tig + 4) * SMS + m];
                ah[mf][3] = Ah[(kk + tig + 4) * SMS + m + 8];
                al[mf][0] = Al[(kk + tig) * SMS + m];
                al[mf][1] = Al[(kk + tig) * SMS + m + 8];
                al[mf][2] = Al[(kk + tig + 4) * SMS + m];
                al[mf][3] = Al[(kk + tig + 4) * SMS + m + 8];
            }
            #pragma unroll
            for (int nf = 0; nf < 4; nf++) {
                int n = wn + nf * 8 + gid;
                bh[nf][0] = Bh[(kk + tig) * SMS + n];
                bh[nf][1] = Bh[(kk + tig + 4) * SMS + n];
                bl[nf][0] = Bl[(kk + tig) * SMS + n];
                bl[nf][1] = Bl[(kk + tig + 4) * SMS + n];
            }
            #pragma unroll
            for (int mf = 0; mf < 4; mf++)
                #pragma unroll
                for (int nf = 0; nf < 4; nf++) {
                    mma8(acc[mf][nf], ah[mf], bl[nf]);
                    mma8(acc[mf][nf], al[mf], bh[nf]);
                    mma8(acc[mf][nf], ah[mf], bh[nf]);
                }
        }
        __syncthreads();
    }

    // ---- partial softmax stats over the 128 rows of this tile, per column ----
    #pragma unroll
    for (int nf = 0; nf < 4; nf++) {
        #pragma unroll
        for (int h = 0; h < 2; h++) {
            float mx = -1e30f;
            #pragma unroll
            for (int mf = 0; mf < 4; mf++)
                mx = fmaxf(mx, fmaxf(acc[mf][nf][h], acc[mf][nf][2 + h]));
            float sum = 0.f;
            #pragma unroll
            for (int mf = 0; mf < 4; mf++)
                sum += __expf(acc[mf][nf][h] - mx) + __expf(acc[mf][nf][2 + h] - mx);
            #pragma unroll
            for (int off = 4; off < 32; off <<= 1) {
                float mo = __shfl_xor_sync(0xffffffffu, mx, off);
                float so = __shfl_xor_sync(0xffffffffu, sum, off);
                float mn = fmaxf(mx, mo);
                sum = sum * __expf(mx - mn) + so * __expf(mo - mn);
                mx = mn;
            }
            if (gid == 0) {
                int col = wn + nf * 8 + 2 * tig + h;
                pm_sh[wid & 1][col] = mx;
                ps_sh[wid & 1][col] = sum;
            }
        }
    }
    __syncthreads();
    if (tid < 128) {
        float m0 = pm_sh[0][tid], m1 = pm_sh[1][tid];
        float mn = fmaxf(m0, m1);
        float s = ps_sh[0][tid] * __expf(m0 - mn) + ps_sh[1][tid] * __expf(m1 - mn);
        g_pm[lt][b][p0 + tid] = mn;
        g_ps[lt][b][p0 + tid] = s;
    }

    // ---- store S tile ----
    #pragma unroll
    for (int mf = 0; mf < 4; mf++) {
        #pragma unroll
        for (int nf = 0; nf < 4; nf++) {
            int r = l0 + wm + mf * 16 + gid;
            int cc = p0 + wn + nf * 8 + 2 * tig;
            *(float2*)&g_S[b][r][cc]     = make_float2(acc[mf][nf][0], acc[mf][nf][1]);
            *(float2*)&g_S[b][r + 8][cc] = make_float2(acc[mf][nf][2], acc[mf][nf][3]);
        }
    }
}

// ---------------------------------------------------------------------------
// combine 32 per-tile partials per column (proven)
// ---------------------------------------------------------------------------
__global__ void softmax_combine() {
    int idx = blockIdx.x * blockDim.x + threadIdx.x;
    int b = idx >> 12;
    int p = idx & (HW - 1);
    float m = g_pm[0][b][p];
    float s = g_ps[0][b][p];
    #pragma unroll
    for (int t = 1; t < NTILES; t++) {
        float mt = g_pm[t][b][p];
        float st = g_ps[t][b][p];
        float mn = fmaxf(m, mt);
        s = s * __expf(m - mn) + st * __expf(mt - mn);
        m = mn;
    }
    g_cmax[b][p] = m;
    g_crcp[b][p] = 1.f / s;
}

// ---------------------------------------------------------------------------
// gemm2 (PROVEN R2 fp32 FFMA kernel, verbatim):
// R = K^T (128x4096) @ softmax(S) (4096x4096), exp fused into B-load,
// masked-blend output epilogue.
// ---------------------------------------------------------------------------
__global__ __launch_bounds__(256) void gemm2(const float* __restrict__ fg,
                                             const float* __restrict__ mask,
                                             float* __restrict__ out) {
    int b  = blockIdx.z;
    int p0 = blockIdx.x * BN;
    __shared__ float As[BK][BM];     // [l][c]
    __shared__ float Bs[BK][BN];     // [l][p], exp-normalized
    __shared__ float sm[BN], sr[BN], smk[BN];
    int tid = threadIdx.x;
    int tx = tid & 15, ty = tid >> 4;
    if (tid < BN) {
        sm[tid]  = g_cmax[b][p0 + tid];
        sr[tid]  = g_crcp[b][p0 + tid];
        smk[tid] = mask[b * HW + p0 + tid];
    }
    __syncthreads();
    float acc[8][8] = {};

    for (int l0 = 0; l0 < HW; l0 += BK) {
        #pragma unroll
        for (int k = 0; k < 2; k++) {
            int f = tid * 2 + k;
            int row = f >> 5;                    // l-local 0..15
            int c4  = (f & 31) * 4;              // c
            *(float4*)&As[row][c4] = *(const float4*)&g_k[b][l0 + row][c4];
        }
        #pragma unroll
        for (int k = 0; k < 2; k++) {
            int f = tid * 2 + k;
            int row = f >> 5;                    // l-local
            int p4  = (f & 31) * 4;              // p-local
            float4 v = *(const float4*)&g_S[b][l0 + row][p0 + p4];
            v.x = __expf(v.x - sm[p4 + 0]) * sr[p4 + 0];
            v.y = __expf(v.y - sm[p4 + 1]) * sr[p4 + 1];
            v.z = __expf(v.z - sm[p4 + 2]) * sr[p4 + 2];
            v.w = __expf(v.w - sm[p4 + 3]) * sr[p4 + 3];
            *(float4*)&Bs[row][p4] = v;
        }
        __syncthreads();
        #pragma unroll
        for (int kk = 0; kk < BK; kk++) {
            float a[8], bb[8];
            *(float4*)&a[0]  = *(const float4*)&As[kk][ty * 8];
            *(float4*)&a[4]  = *(const float4*)&As[kk][ty * 8 + 4];
            *(float4*)&bb[0] = *(const float4*)&Bs[kk][tx * 8];
            *(float4*)&bb[4] = *(const float4*)&Bs[kk][tx * 8 + 4];
            #pragma unroll
            for (int i = 0; i < 8; i++)
                #pragma unroll
                for (int j = 0; j < 8; j++)
                    acc[i][j] += a[i] * bb[j];
        }
        __syncthreads();
    }
    // epilogue: out = R*(1-m)/9 + x*m
    #pragma unroll
    for (int i = 0; i < 8; i++) {
        int c = ty * 8 + i;
        const float* frow = fg  + ((size_t)(b * C + c)) * HW + p0;
        float*       orow = out + ((size_t)(b * C + c)) * HW + p0;
        #pragma unroll
        for (int j = 0; j < 8; j++) {
            int pl = tx * 8 + j;
            float mk = smk[pl];
            orow[pl] = acc[i][j] * (1.f - mk) * (1.f / 9.f) + frow[pl] * mk;
        }
    }
}

extern "C" void kernel_launch(void* const* d_in, const int* in_sizes, int n_in,
                              void* d_out, int out_size) {
    const float* fg   = (const float*)d_in[0];
    const float* mask = (const float*)d_in[1];
    float* out = (float*)d_out;

    k_prep<<<dim3(HW, NB), C>>>(fg);
    y_prep<<<(NB * C * HW) / 256, 256>>>(fg);
    gemm1_mma<<<dim3(HW / 128, HW / 128, NB), 256>>>();
    softmax_combine<<<(NB * HW) / 256, 256>>>();
    gemm2<<<dim3(HW / BN, 1, NB), 256>>>(fg, mask, out);
}

// round 9
// speedup vs baseline: 2.2072x; 1.6701x over previous
#include <cuda_runtime.h>
#include <cuda_bf16.h>
#include <cstdint>

#define NB 4
#define C 128
#define HW 4096
#define EPSF 1e-7f
#define NTILES (HW / 128)
#define SMS 136   // padded shared stride (uint32 units)

// ---------------- scratch ----------------
__device__ __align__(128) float g_k [NB][HW][C];    // K[l][c]
__device__ __align__(128) float g_y [NB][C][HW];    // boxsum [c][p]
__device__ __align__(128) float g_S [NB][HW][HW];   // S[l][p]
__device__ float g_pm[NTILES][NB][HW];
__device__ float g_ps[NTILES][NB][HW];
__device__ float g_cmax[NB][HW];
__device__ float g_crcp[NB][HW];

// ---------------- helpers ----------------
// split (v0, v1) [consecutive k] into packed bf16x2 hi + lo (even k in low half)
__device__ __forceinline__ void bf_split2(float v0, float v1, uint32_t& h, uint32_t& l) {
    __nv_bfloat16 h0 = __float2bfloat16(v0);
    __nv_bfloat16 h1 = __float2bfloat16(v1);
    __nv_bfloat16 l0 = __float2bfloat16(v0 - __bfloat162float(h0));
    __nv_bfloat16 l1 = __float2bfloat16(v1 - __bfloat162float(h1));
    h = (uint32_t)__bfloat16_as_ushort(h0) | ((uint32_t)__bfloat16_as_ushort(h1) << 16);
    l = (uint32_t)__bfloat16_as_ushort(l0) | ((uint32_t)__bfloat16_as_ushort(l1) << 16);
}
__device__ __forceinline__ void mma16(float* c, const uint32_t* a, const uint32_t* b) {
    asm volatile("mma.sync.aligned.m16n8k16.row.col.f32.bf16.bf16.f32 "
        "{%0,%1,%2,%3},{%4,%5,%6,%7},{%8,%9},{%0,%1,%2,%3};"
        : "+f"(c[0]), "+f"(c[1]), "+f"(c[2]), "+f"(c[3])
        : "r"(a[0]), "r"(a[1]), "r"(a[2]), "r"(a[3]), "r"(b[0]), "r"(b[1]));
}

// ---------------------------------------------------------------------------
// prep (proven)
// ---------------------------------------------------------------------------
__global__ void k_prep(const float* __restrict__ fg) {
    int l = blockIdx.x, b = blockIdx.y, c = threadIdx.x;
    float v = fg[((b * C + c) * HW) + l] + EPSF;
    float s = v * v;
    #pragma unroll
    for (int o = 16; o > 0; o >>= 1) s += __shfl_xor_sync(0xffffffffu, s, o);
    __shared__ float ws[4];
    if ((c & 31) == 0) ws[c >> 5] = s;
    __syncthreads();
    float tot = ws[0] + ws[1] + ws[2] + ws[3];
    g_k[b][l][c] = v * rsqrtf(tot);
}

__global__ void y_prep(const float* __restrict__ fg) {
    int idx = blockIdx.x * blockDim.x + threadIdx.x;
    int p = idx & (HW - 1);
    int bc = idx >> 12;
    int i = p >> 6, j = p & 63;
    const float* base = fg + (size_t)bc * HW;
    float s = 0.f;
    #pragma unroll
    for (int di = -1; di <= 1; di++) {
        int ii = i + di;
        if (ii < 0 || ii >= 64) continue;
        #pragma unroll
        for (int dj = -1; dj <= 1; dj++) {
            int jj = j + dj;
            if (jj < 0 || jj >= 64) continue;
            s += base[ii * 64 + jj];
        }
    }
    ((float*)g_y)[idx] = s;
}

// ---------------------------------------------------------------------------
// gemm1 (split-bf16 m16n8k16): S[l][p] = K[l][:] . Y[:,p]  + partial stats
// block 256 = 8 warps (2m x 4n), warp tile 64x32, BK=32 (16 k-pairs)
// smem layout: X[(k_pair)*SMS + col]
// ---------------------------------------------------------------------------
__global__ __launch_bounds__(256) void gemm1_mma() {
    __shared__ uint32_t Ah[16 * SMS], Al[16 * SMS];   // [k2][m]
    __shared__ uint32_t Bh[16 * SMS], Bl[16 * SMS];   // [k2][n]
    __shared__ float pm_sh[2][128], ps_sh[2][128];

    int b = blockIdx.z, lt = blockIdx.y;
    int l0 = lt * 128, p0 = blockIdx.x * 128;
    int tid = threadIdx.x, wid = tid >> 5, lane = tid & 31;
    int gid = lane >> 2, tig = lane & 3;
    int wm = (wid & 1) * 64, wn = (wid >> 1) * 32;

    float acc[4][4][4] = {};
    const float* Ag = &g_k[b][l0][0];   // rows = m (l), cols = k (c)
    const float* Bg = &g_y[b][0][p0];   // rows = k (c), cols = n (p)

    int am = tid & 127, ap = (tid >> 7) * 8;   // A: row am, pairs [ap, ap+8)
    int pr = tid >> 4,  bn = (tid & 15) * 8;   // B: pair-row pr, n [bn, bn+8)

    for (int c0 = 0; c0 < C; c0 += 32) {
        // A: k contiguous in source row -> easy pair packing
        #pragma unroll
        for (int i = 0; i < 4; i++) {
            float4 v = *(const float4*)(Ag + am * C + c0 + ap * 2 + i * 4);
            int p2 = ap + i * 2;
            uint32_t h, l;
            bf_split2(v.x, v.y, h, l); Ah[p2 * SMS + am] = h;       Al[p2 * SMS + am] = l;
            bf_split2(v.z, v.w, h, l); Ah[(p2 + 1) * SMS + am] = h; Al[(p2 + 1) * SMS + am] = l;
        }
        // B: pairs span two consecutive k-rows
        #pragma unroll
        for (int i = 0; i < 2; i++) {
            float4 v0 = *(const float4*)(Bg + (size_t)(c0 + 2 * pr)     * HW + bn + i * 4);
            float4 v1 = *(const float4*)(Bg + (size_t)(c0 + 2 * pr + 1) * HW + bn + i * 4);
            uint4 uh, ul;
            bf_split2(v0.x, v1.x, uh.x, ul.x);
            bf_split2(v0.y, v1.y, uh.y, ul.y);
            bf_split2(v0.z, v1.z, uh.z, ul.z);
            bf_split2(v0.w, v1.w, uh.w, ul.w);
            *(uint4*)&Bh[pr * SMS + bn + i * 4] = uh;
            *(uint4*)&Bl[pr * SMS + bn + i * 4] = ul;
        }
        __syncthreads();
        #pragma unroll
        for (int kk2 = 0; kk2 < 16; kk2 += 8) {
            uint32_t ah[4][4], al[4][4], bh[4][2], bl[4][2];
            #pragma unroll
            for (int mf = 0; mf < 4; mf++) {
                int m = wm + mf * 16 + gid;
                ah[mf][0] = Ah[(kk2 + tig) * SMS + m];
                ah[mf][1] = Ah[(kk2 + tig) * SMS + m + 8];
                ah[mf][2] = Ah[(kk2 + tig + 4) * SMS + m];
                ah[mf][3] = Ah[(kk2 + tig + 4) * SMS + m + 8];
                al[mf][0] = Al[(kk2 + tig) * SMS + m];
                al[mf][1] = Al[(kk2 + tig) * SMS + m + 8];
                al[mf][2] = Al[(kk2 + tig + 4) * SMS + m];
                al[mf][3] = Al[(kk2 + tig + 4) * SMS + m + 8];
            }
            #pragma unroll
            for (int nf = 0; nf < 4; nf++) {
                int n = wn + nf * 8 + gid;
                bh[nf][0] = Bh[(kk2 + tig) * SMS + n];
                bh[nf][1] = Bh[(kk2 + tig + 4) * SMS + n];
                bl[nf][0] = Bl[(kk2 + tig) * SMS + n];
                bl[nf][1] = Bl[(kk2 + tig + 4) * SMS + n];
            }
            #pragma unroll
            for (int mf = 0; mf < 4; mf++)
                #pragma unroll
                for (int nf = 0; nf < 4; nf++) {
                    mma16(acc[mf][nf], ah[mf], bl[nf]);
                    mma16(acc[mf][nf], al[mf], bh[nf]);
                    mma16(acc[mf][nf], ah[mf], bh[nf]);
                }
        }
        __syncthreads();
    }

    // ---- partial softmax stats (proven) ----
    #pragma unroll
    for (int nf = 0; nf < 4; nf++) {
        #pragma unroll
        for (int h = 0; h < 2; h++) {
            float mx = -1e30f;
            #pragma unroll
            for (int mf = 0; mf < 4; mf++)
                mx = fmaxf(mx, fmaxf(acc[mf][nf][h], acc[mf][nf][2 + h]));
            float sum = 0.f;
            #pragma unroll
            for (int mf = 0; mf < 4; mf++)
                sum += __expf(acc[mf][nf][h] - mx) + __expf(acc[mf][nf][2 + h] - mx);
            #pragma unroll
            for (int off = 4; off < 32; off <<= 1) {
                float mo = __shfl_xor_sync(0xffffffffu, mx, off);
                float so = __shfl_xor_sync(0xffffffffu, sum, off);
                float mn = fmaxf(mx, mo);
                sum = sum * __expf(mx - mn) + so * __expf(mo - mn);
                mx = mn;
            }
            if (gid == 0) {
                int col = wn + nf * 8 + 2 * tig + h;
                pm_sh[wid & 1][col] = mx;
                ps_sh[wid & 1][col] = sum;
            }
        }
    }
    __syncthreads();
    if (tid < 128) {
        float m0 = pm_sh[0][tid], m1 = pm_sh[1][tid];
        float mn = fmaxf(m0, m1);
        float s = ps_sh[0][tid] * __expf(m0 - mn) + ps_sh[1][tid] * __expf(m1 - mn);
        g_pm[lt][b][p0 + tid] = mn;
        g_ps[lt][b][p0 + tid] = s;
    }

    // ---- store S tile (proven) ----
    #pragma unroll
    for (int mf = 0; mf < 4; mf++) {
        #pragma unroll
        for (int nf = 0; nf < 4; nf++) {
            int r = l0 + wm + mf * 16 + gid;
            int cc = p0 + wn + nf * 8 + 2 * tig;
            *(float2*)&g_S[b][r][cc]     = make_float2(acc[mf][nf][0], acc[mf][nf][1]);
            *(float2*)&g_S[b][r + 8][cc] = make_float2(acc[mf][nf][2], acc[mf][nf][3]);
        }
    }
}

// ---------------------------------------------------------------------------
// combine (proven)
// ---------------------------------------------------------------------------
__global__ void softmax_combine() {
    int idx = blockIdx.x * blockDim.x + threadIdx.x;
    int b = idx >> 12;
    int p = idx & (HW - 1);
    float m = g_pm[0][b][p];
    float s = g_ps[0][b][p];
    #pragma unroll
    for (int t = 1; t < NTILES; t++) {
        float mt = g_pm[t][b][p];
        float st = g_ps[t][b][p];
        float mn = fmaxf(m, mt);
        s = s * __expf(m - mn) + st * __expf(mt - mn);
        m = mn;
    }
    g_cmax[b][p] = m;
    g_crcp[b][p] = 1.f / s;
}

// ---------------------------------------------------------------------------
// gemm2 (split-bf16 m16n8k16): out[c][p] = sum_l K[l][c] * softmax(S)[l][p]
// A loaded straight from g_k rows (transposed pair-packing in smem store);
// exp fused into B-load; mask blend epilogue.  BK=32.
// ---------------------------------------------------------------------------
__global__ __launch_bounds__(256) void gemm2_mma(const float* __restrict__ fg,
                                                 const float* __restrict__ mask,
                                                 float* __restrict__ out) {
    __shared__ uint32_t Ah[16 * SMS], Al[16 * SMS];   // [l2][c]
    __shared__ uint32_t Bh[16 * SMS], Bl[16 * SMS];   // [l2][p]
    __shared__ float sm[128], sr[128], smk[128];

    int b = blockIdx.y, p0 = blockIdx.x * 128;
    int tid = threadIdx.x, wid = tid >> 5, lane = tid & 31;
    int gid = lane >> 2, tig = lane & 3;
    int wm = (wid & 1) * 64, wn = (wid >> 1) * 32;

    if (tid < 128) {
        sm[tid]  = g_cmax[b][p0 + tid];
        sr[tid]  = g_crcp[b][p0 + tid];
        smk[tid] = mask[b * HW + p0 + tid];
    }
    __syncthreads();

    float acc[4][4][4] = {};
    const float* Kg = &g_k[b][0][0];   // rows = l (k-dim), cols = c (m)
    const float* Sg = &g_S[b][0][0];   // rows = l (k-dim), cols = p (n)

    int pr = tid >> 4;                 // pair-row 0..15
    int cn = (tid & 15) * 8;           // column range [cn, cn+8)

    for (int l0 = 0; l0 < HW; l0 += 32) {
        // A: K^T — pairs span two consecutive l-rows of g_k
        #pragma unroll
        for (int i = 0; i < 2; i++) {
            float4 v0 = *(const float4*)(Kg + (size_t)(l0 + 2 * pr)     * C + cn + i * 4);
            float4 v1 = *(const float4*)(Kg + (size_t)(l0 + 2 * pr + 1) * C + cn + i * 4);
            uint4 uh, ul;
            bf_split2(v0.x, v1.x, uh.x, ul.x);
            bf_split2(v0.y, v1.y, uh.y, ul.y);
            bf_split2(v0.z, v1.z, uh.z, ul.z);
            bf_split2(v0.w, v1.w, uh.w, ul.w);
            *(uint4*)&Ah[pr * SMS + cn + i * 4] = uh;
            *(uint4*)&Al[pr * SMS + cn + i * 4] = ul;
        }
        // B: softmax weights — exp applied per element, pairs span two l-rows
        #pragma unroll
        for (int i = 0; i < 2; i++) {
            int n = cn + i * 4;
            float4 v0 = *(const float4*)(Sg + (size_t)(l0 + 2 * pr)     * HW + p0 + n);
            float4 v1 = *(const float4*)(Sg + (size_t)(l0 + 2 * pr + 1) * HW + p0 + n);
            v0.x = __expf(v0.x - sm[n + 0]) * sr[n + 0];
            v0.y = __expf(v0.y - sm[n + 1]) * sr[n + 1];
            v0.z = __expf(v0.z - sm[n + 2]) * sr[n + 2];
            v0.w = __expf(v0.w - sm[n + 3]) * sr[n + 3];
            v1.x = __expf(v1.x - sm[n + 0]) * sr[n + 0];
            v1.y = __expf(v1.y - sm[n + 1]) * sr[n + 1];
            v1.z = __expf(v1.z - sm[n + 2]) * sr[n + 2];
            v1.w = __expf(v1.w - sm[n + 3]) * sr[n + 3];
            uint4 uh, ul;
            bf_split2(v0.x, v1.x, uh.x, ul.x);
            bf_split2(v0.y, v1.y, uh.y, ul.y);
            bf_split2(v0.z, v1.z, uh.z, ul.z);
            bf_split2(v0.w, v1.w, uh.w, ul.w);
            *(uint4*)&Bh[pr * SMS + n] = uh;
            *(uint4*)&Bl[pr * SMS + n] = ul;
        }
        __syncthreads();
        #pragma unroll
        for (int kk2 = 0; kk2 < 16; kk2 += 8) {
            uint32_t ah[4][4], al[4][4], bh[4][2], bl[4][2];
            #pragma unroll
            for (int mf = 0; mf < 4; mf++) {
                int m = wm + mf * 16 + gid;
                ah[mf][0] = Ah[(kk2 + tig) * SMS + m];
                ah[mf][1] = Ah[(kk2 + tig) * SMS + m + 8];
                ah[mf][2] = Ah[(kk2 + tig + 4) * SMS + m];
                ah[mf][3] = Ah[(kk2 + tig + 4) * SMS + m + 8];
                al[mf][0] = Al[(kk2 + tig) * SMS + m];
                al[mf][1] = Al[(kk2 + tig) * SMS + m + 8];
                al[mf][2] = Al[(kk2 + tig + 4) * SMS + m];
                al[mf][3] = Al[(kk2 + tig + 4) * SMS + m + 8];
            }
            #pragma unroll
            for (int nf = 0; nf < 4; nf++) {
                int n = wn + nf * 8 + gid;
                bh[nf][0] = Bh[(kk2 + tig) * SMS + n];
                bh[nf][1] = Bh[(kk2 + tig + 4) * SMS + n];
                bl[nf][0] = Bl[(kk2 + tig) * SMS + n];
                bl[nf][1] = Bl[(kk2 + tig + 4) * SMS + n];
            }
            #pragma unroll
            for (int mf = 0; mf < 4; mf++)
                #pragma unroll
                for (int nf = 0; nf < 4; nf++) {
                    mma16(acc[mf][nf], ah[mf], bl[nf]);
                    mma16(acc[mf][nf], al[mf], bh[nf]);
                    mma16(acc[mf][nf], ah[mf], bh[nf]);
                }
        }
        __syncthreads();
    }

    // epilogue: out = acc*(1-m)/9 + x*m  (same index pattern as proven S store)
    #pragma unroll
    for (int mf = 0; mf < 4; mf++) {
        #pragma unroll
        for (int nf = 0; nf < 4; nf++) {
            int nl = wn + nf * 8 + 2 * tig;
            float mk0 = smk[nl], mk1 = smk[nl + 1];
            int c = wm + mf * 16 + gid;
            {
                const float* frow = fg  + ((size_t)(b * C + c)) * HW + p0 + nl;
                float*       orow = out + ((size_t)(b * C + c)) * HW + p0 + nl;
                float2 fx = *(const float2*)frow;
                float2 o;
                o.x = acc[mf][nf][0] * (1.f - mk0) * (1.f / 9.f) + fx.x * mk0;
                o.y = acc[mf][nf][1] * (1.f - mk1) * (1.f / 9.f) + fx.y * mk1;
                *(float2*)orow = o;
            }
            {
                const float* frow = fg  + ((size_t)(b * C + c + 8)) * HW + p0 + nl;
                float*       orow = out + ((size_t)(b * C + c + 8)) * HW + p0 + nl;
                float2 fx = *(const float2*)frow;
                float2 o;
                o.x = acc[mf][nf][2] * (1.f - mk0) * (1.f / 9.f) + fx.x * mk0;
                o.y = acc[mf][nf][3] * (1.f - mk1) * (1.f / 9.f) + fx.y * mk1;
                *(float2*)orow = o;
            }
        }
    }
}

extern "C" void kernel_launch(void* const* d_in, const int* in_sizes, int n_in,
                              void* d_out, int out_size) {
    const float* fg   = (const float*)d_in[0];
    const float* mask = (const float*)d_in[1];
    float* out = (float*)d_out;

    k_prep<<<dim3(HW, NB), C>>>(fg);
    y_prep<<<(NB * C * HW) / 256, 256>>>(fg);
    gemm1_mma<<<dim3(HW / 128, HW / 128, NB), 256>>>();
    softmax_combine<<<(NB * HW) / 256, 256>>>();
    gemm2_mma<<<dim3(HW / 128, NB), 256>>>(fg, mask, out);
}

// round 10
// speedup vs baseline: 2.9565x; 1.3395x over previous
#include <cuda_runtime.h>
#include <cuda_bf16.h>
#include <cstdint>

#define NB 4
#define C 128
#define HW 4096
#define EPSF 1e-7f
#define NTILES (HW / 128)
#define SMS 136      // padded shared stride (uint32 units)
#define KSPLIT 4

// ---------------- scratch ----------------
__device__ __align__(128) float g_k [NB][HW][C];    // K[l][c]
__device__ __align__(128) float g_y [NB][C][HW];    // boxsum [c][p]
__device__ __align__(128) float g_S [NB][HW][HW];   // S[l][p]
__device__ __align__(128) float g_part[KSPLIT][NB][C][HW];  // gemm2 split-K partials
__device__ float g_pm[NTILES][NB][HW];
__device__ float g_ps[NTILES][NB][HW];
__device__ float g_cmax[NB][HW];
__device__ float g_crcp[NB][HW];

// ---------------- helpers (proven) ----------------
__device__ __forceinline__ void bf_split2(float v0, float v1, uint32_t& h, uint32_t& l) {
    __nv_bfloat16 h0 = __float2bfloat16(v0);
    __nv_bfloat16 h1 = __float2bfloat16(v1);
    __nv_bfloat16 l0 = __float2bfloat16(v0 - __bfloat162float(h0));
    __nv_bfloat16 l1 = __float2bfloat16(v1 - __bfloat162float(h1));
    h = (uint32_t)__bfloat16_as_ushort(h0) | ((uint32_t)__bfloat16_as_ushort(h1) << 16);
    l = (uint32_t)__bfloat16_as_ushort(l0) | ((uint32_t)__bfloat16_as_ushort(l1) << 16);
}
__device__ __forceinline__ void mma16(float* c, const uint32_t* a, const uint32_t* b) {
    asm volatile("mma.sync.aligned.m16n8k16.row.col.f32.bf16.bf16.f32 "
        "{%0,%1,%2,%3},{%4,%5,%6,%7},{%8,%9},{%0,%1,%2,%3};"
        : "+f"(c[0]), "+f"(c[1]), "+f"(c[2]), "+f"(c[3])
        : "r"(a[0]), "r"(a[1]), "r"(a[2]), "r"(a[3]), "r"(b[0]), "r"(b[1]));
}

// one BK=16 stage of 3-term split-bf16 mma (proven fragment mapping, kk2=0 only)
__device__ __forceinline__ void mma_block(const uint32_t* pAh, const uint32_t* pAl,
                                          const uint32_t* pBh, const uint32_t* pBl,
                                          int wm, int wn, int gid, int tig,
                                          float acc[4][4][4]) {
    uint32_t ah[4][4], al[4][4], bh[4][2], bl[4][2];
    #pragma unroll
    for (int mf = 0; mf < 4; mf++) {
        int m = wm + mf * 16 + gid;
        ah[mf][0] = pAh[tig * SMS + m];
        ah[mf][1] = pAh[tig * SMS + m + 8];
        ah[mf][2] = pAh[(tig + 4) * SMS + m];
        ah[mf][3] = pAh[(tig + 4) * SMS + m + 8];
        al[mf][0] = pAl[tig * SMS + m];
        al[mf][1] = pAl[tig * SMS + m + 8];
        al[mf][2] = pAl[(tig + 4) * SMS + m];
        al[mf][3] = pAl[(tig + 4) * SMS + m + 8];
    }
    #pragma unroll
    for (int nf = 0; nf < 4; nf++) {
        int n = wn + nf * 8 + gid;
        bh[nf][0] = pBh[tig * SMS + n];
        bh[nf][1] = pBh[(tig + 4) * SMS + n];
        bl[nf][0] = pBl[tig * SMS + n];
        bl[nf][1] = pBl[(tig + 4) * SMS + n];
    }
    #pragma unroll
    for (int mf = 0; mf < 4; mf++)
        #pragma unroll
        for (int nf = 0; nf < 4; nf++) {
            mma16(acc[mf][nf], ah[mf], bl[nf]);
            mma16(acc[mf][nf], al[mf], bh[nf]);
            mma16(acc[mf][nf], ah[mf], bh[nf]);
        }
}

// ---------------------------------------------------------------------------
// prep (proven)
// ---------------------------------------------------------------------------
__global__ void k_prep(const float* __restrict__ fg) {
    int l = blockIdx.x, b = blockIdx.y, c = threadIdx.x;
    float v = fg[((b * C + c) * HW) + l] + EPSF;
    float s = v * v;
    #pragma unroll
    for (int o = 16; o > 0; o >>= 1) s += __shfl_xor_sync(0xffffffffu, s, o);
    __shared__ float ws[4];
    if ((c & 31) == 0) ws[c >> 5] = s;
    __syncthreads();
    float tot = ws[0] + ws[1] + ws[2] + ws[3];
    g_k[b][l][c] = v * rsqrtf(tot);
}

__global__ void y_prep(const float* __restrict__ fg) {
    int idx = blockIdx.x * blockDim.x + threadIdx.x;
    int p = idx & (HW - 1);
    int bc = idx >> 12;
    int i = p >> 6, j = p & 63;
    const float* base = fg + (size_t)bc * HW;
    float s = 0.f;
    #pragma unroll
    for (int di = -1; di <= 1; di++) {
        int ii = i + di;
        if (ii < 0 || ii >= 64) continue;
        #pragma unroll
        for (int dj = -1; dj <= 1; dj++) {
            int jj = j + dj;
            if (jj < 0 || jj >= 64) continue;
            s += base[ii * 64 + jj];
        }
    }
    ((float*)g_y)[idx] = s;
}

// ---------------------------------------------------------------------------
// gemm1: S[l][p] = K[l][:] . Y[:,p]  + partial stats
// double-buffered BK=16, 8 chunks, one sync per chunk
// ---------------------------------------------------------------------------
__global__ __launch_bounds__(256) void gemm1_mma() {
    __shared__ uint32_t sh[2][4][8 * SMS];   // [stage][Ah,Al,Bh,Bl][k2*SMS+col]
    __shared__ float pm_sh[2][128], ps_sh[2][128];

    int b = blockIdx.z, lt = blockIdx.y;
    int l0 = lt * 128, p0 = blockIdx.x * 128;
    int tid = threadIdx.x, wid = tid >> 5, lane = tid & 31;
    int gid = lane >> 2, tig = lane & 3;
    int wm = (wid & 1) * 64, wn = (wid >> 1) * 32;

    const float* Ag = &g_k[b][l0][0];   // rows = m (l), cols = k (c)
    const float* Bg = &g_y[b][0][p0];   // rows = k (c), cols = n (p)

    int am = tid & 127, ah4 = (tid >> 7) * 4;   // A: row am, pairs [ah4, ah4+4)
    int pr = tid >> 5,  bn = (tid & 31) * 4;    // B: pair-row pr, n [bn, bn+4)

    float4 a0, a1, b0, b1;
    a0 = *(const float4*)(Ag + am * C + ah4 * 2);
    a1 = *(const float4*)(Ag + am * C + ah4 * 2 + 4);
    b0 = *(const float4*)(Bg + (size_t)(2 * pr) * HW + bn);
    b1 = *(const float4*)(Bg + (size_t)(2 * pr + 1) * HW + bn);
    {
        uint32_t h, l;
        bf_split2(a0.x, a0.y, h, l); sh[0][0][(ah4+0)*SMS+am] = h; sh[0][1][(ah4+0)*SMS+am] = l;
        bf_split2(a0.z, a0.w, h, l); sh[0][0][(ah4+1)*SMS+am] = h; sh[0][1][(ah4+1)*SMS+am] = l;
        bf_split2(a1.x, a1.y, h, l); sh[0][0][(ah4+2)*SMS+am] = h; sh[0][1][(ah4+2)*SMS+am] = l;
        bf_split2(a1.z, a1.w, h, l); sh[0][0][(ah4+3)*SMS+am] = h; sh[0][1][(ah4+3)*SMS+am] = l;
        uint4 uh, ul;
        bf_split2(b0.x, b1.x, uh.x, ul.x);
        bf_split2(b0.y, b1.y, uh.y, ul.y);
        bf_split2(b0.z, b1.z, uh.z, ul.z);
        bf_split2(b0.w, b1.w, uh.w, ul.w);
        *(uint4*)&sh[0][2][pr*SMS+bn] = uh;
        *(uint4*)&sh[0][3][pr*SMS+bn] = ul;
    }
    __syncthreads();

    float acc[4][4][4] = {};
    for (int it = 0; it < 8; it++) {
        int st = it & 1;
        if (it < 7) {
            int c0 = (it + 1) * 16;
            a0 = *(const float4*)(Ag + am * C + c0 + ah4 * 2);
            a1 = *(const float4*)(Ag + am * C + c0 + ah4 * 2 + 4);
            b0 = *(const float4*)(Bg + (size_t)(c0 + 2 * pr) * HW + bn);
            b1 = *(const float4*)(Bg + (size_t)(c0 + 2 * pr + 1) * HW + bn);
        }
        mma_block(sh[st][0], sh[st][1], sh[st][2], sh[st][3], wm, wn, gid, tig, acc);
        if (it < 7) {
            int ns = st ^ 1;
            uint32_t h, l;
            bf_split2(a0.x, a0.y, h, l); sh[ns][0][(ah4+0)*SMS+am] = h; sh[ns][1][(ah4+0)*SMS+am] = l;
            bf_split2(a0.z, a0.w, h, l); sh[ns][0][(ah4+1)*SMS+am] = h; sh[ns][1][(ah4+1)*SMS+am] = l;
            bf_split2(a1.x, a1.y, h, l); sh[ns][0][(ah4+2)*SMS+am] = h; sh[ns][1][(ah4+2)*SMS+am] = l;
            bf_split2(a1.z, a1.w, h, l); sh[ns][0][(ah4+3)*SMS+am] = h; sh[ns][1][(ah4+3)*SMS+am] = l;
            uint4 uh, ul;
            bf_split2(b0.x, b1.x, uh.x, ul.x);
            bf_split2(b0.y, b1.y, uh.y, ul.y);
            bf_split2(b0.z, b1.z, uh.z, ul.z);
            bf_split2(b0.w, b1.w, uh.w, ul.w);
            *(uint4*)&sh[ns][2][pr*SMS+bn] = uh;
            *(uint4*)&sh[ns][3][pr*SMS+bn] = ul;
            __syncthreads();
        }
    }

    // ---- partial softmax stats (proven) ----
    #pragma unroll
    for (int nf = 0; nf < 4; nf++) {
        #pragma unroll
        for (int h = 0; h < 2; h++) {
            float mx = -1e30f;
            #pragma unroll
            for (int mf = 0; mf < 4; mf++)
                mx = fmaxf(mx, fmaxf(acc[mf][nf][h], acc[mf][nf][2 + h]));
            float sum = 0.f;
            #pragma unroll
            for (int mf = 0; mf < 4; mf++)
                sum += __expf(acc[mf][nf][h] - mx) + __expf(acc[mf][nf][2 + h] - mx);
            #pragma unroll
            for (int off = 4; off < 32; off <<= 1) {
                float mo = __shfl_xor_sync(0xffffffffu, mx, off);
                float so = __shfl_xor_sync(0xffffffffu, sum, off);
                float mn = fmaxf(mx, mo);
                sum = sum * __expf(mx - mn) + so * __expf(mo - mn);
                mx = mn;
            }
            if (gid == 0) {
                int col = wn + nf * 8 + 2 * tig + h;
                pm_sh[wid & 1][col] = mx;
                ps_sh[wid & 1][col] = sum;
            }
        }
    }
    __syncthreads();
    if (tid < 128) {
        float m0 = pm_sh[0][tid], m1 = pm_sh[1][tid];
        float mn = fmaxf(m0, m1);
        float s = ps_sh[0][tid] * __expf(m0 - mn) + ps_sh[1][tid] * __expf(m1 - mn);
        g_pm[lt][b][p0 + tid] = mn;
        g_ps[lt][b][p0 + tid] = s;
    }

    // ---- store S tile (proven) ----
    #pragma unroll
    for (int mf = 0; mf < 4; mf++) {
        #pragma unroll
        for (int nf = 0; nf < 4; nf++) {
            int r = l0 + wm + mf * 16 + gid;
            int cc = p0 + wn + nf * 8 + 2 * tig;
            *(float2*)&g_S[b][r][cc]     = make_float2(acc[mf][nf][0], acc[mf][nf][1]);
            *(float2*)&g_S[b][r + 8][cc] = make_float2(acc[mf][nf][2], acc[mf][nf][3]);
        }
    }
}

// ---------------------------------------------------------------------------
// combine (proven)
// ---------------------------------------------------------------------------
__global__ void softmax_combine() {
    int idx = blockIdx.x * blockDim.x + threadIdx.x;
    int b = idx >> 12;
    int p = idx & (HW - 1);
    float m = g_pm[0][b][p];
    float s = g_ps[0][b][p];
    #pragma unroll
    for (int t = 1; t < NTILES; t++) {
        float mt = g_pm[t][b][p];
        float st = g_ps[t][b][p];
        float mn = fmaxf(m, mt);
        s = s * __expf(m - mn) + st * __expf(mt - mn);
        m = mn;
    }
    g_cmax[b][p] = m;
    g_crcp[b][p] = 1.f / s;
}

// ---------------------------------------------------------------------------
// gemm2 (split-K x4): g_part[ls][b][c][p] = sum_{l in split} K[l][c]*softmax(S)[l][p]
// double-buffered BK=16, 64 chunks per split, one sync per chunk
// ---------------------------------------------------------------------------
__global__ __launch_bounds__(256) void gemm2_mma() {
    __shared__ uint32_t sh[2][4][8 * SMS];
    __shared__ float sm[128], sr[128];

    int b = blockIdx.y, p0 = blockIdx.x * 128, ls = blockIdx.z;
    int lbase = ls * (HW / KSPLIT);
    int tid = threadIdx.x, wid = tid >> 5, lane = tid & 31;
    int gid = lane >> 2, tig = lane & 3;
    int wm = (wid & 1) * 64, wn = (wid >> 1) * 32;

    if (tid < 128) {
        sm[tid] = g_cmax[b][p0 + tid];
        sr[tid] = g_crcp[b][p0 + tid];
    }
    __syncthreads();

    const float* Kg = &g_k[b][0][0];   // rows = l, cols = c
    const float* Sg = &g_S[b][0][0];   // rows = l, cols = p

    int pr = tid >> 5, cn = (tid & 31) * 4;

    float4 a0, a1, b0, b1;
    a0 = *(const float4*)(Kg + (size_t)(lbase + 2 * pr)     * C + cn);
    a1 = *(const float4*)(Kg + (size_t)(lbase + 2 * pr + 1) * C + cn);
    b0 = *(const float4*)(Sg + (size_t)(lbase + 2 * pr)     * HW + p0 + cn);
    b1 = *(const float4*)(Sg + (size_t)(lbase + 2 * pr + 1) * HW + p0 + cn);
    {
        uint4 uh, ul;
        bf_split2(a0.x, a1.x, uh.x, ul.x);
        bf_split2(a0.y, a1.y, uh.y, ul.y);
        bf_split2(a0.z, a1.z, uh.z, ul.z);
        bf_split2(a0.w, a1.w, uh.w, ul.w);
        *(uint4*)&sh[0][0][pr*SMS+cn] = uh;
        *(uint4*)&sh[0][1][pr*SMS+cn] = ul;
        float4 e0, e1;
        e0.x = __expf(b0.x - sm[cn+0]) * sr[cn+0]; e1.x = __expf(b1.x - sm[cn+0]) * sr[cn+0];
        e0.y = __expf(b0.y - sm[cn+1]) * sr[cn+1]; e1.y = __expf(b1.y - sm[cn+1]) * sr[cn+1];
        e0.z = __expf(b0.z - sm[cn+2]) * sr[cn+2]; e1.z = __expf(b1.z - sm[cn+2]) * sr[cn+2];
        e0.w = __expf(b0.w - sm[cn+3]) * sr[cn+3]; e1.w = __expf(b1.w - sm[cn+3]) * sr[cn+3];
        bf_split2(e0.x, e1.x, uh.x, ul.x);
        bf_split2(e0.y, e1.y, uh.y, ul.y);
        bf_split2(e0.z, e1.z, uh.z, ul.z);
        bf_split2(e0.w, e1.w, uh.w, ul.w);
        *(uint4*)&sh[0][2][pr*SMS+cn] = uh;
        *(uint4*)&sh[0][3][pr*SMS+cn] = ul;
    }
    __syncthreads();

    float acc[4][4][4] = {};
    const int NIT = (HW / KSPLIT) / 16;   // 64
    for (int it = 0; it < NIT; it++) {
        int st = it & 1;
        if (it < NIT - 1) {
            int l0 = lbase + (it + 1) * 16;
            a0 = *(const float4*)(Kg + (size_t)(l0 + 2 * pr)     * C + cn);
            a1 = *(const float4*)(Kg + (size_t)(l0 + 2 * pr + 1) * C + cn);
            b0 = *(const float4*)(Sg + (size_t)(l0 + 2 * pr)     * HW + p0 + cn);
            b1 = *(const float4*)(Sg + (size_t)(l0 + 2 * pr + 1) * HW + p0 + cn);
        }
        mma_block(sh[st][0], sh[st][1], sh[st][2], sh[st][3], wm, wn, gid, tig, acc);
        if (it < NIT - 1) {
            int ns = st ^ 1;
            uint4 uh, ul;
            bf_split2(a0.x, a1.x, uh.x, ul.x);
            bf_split2(a0.y, a1.y, uh.y, ul.y);
            bf_split2(a0.z, a1.z, uh.z, ul.z);
            bf_split2(a0.w, a1.w, uh.w, ul.w);
            *(uint4*)&sh[ns][0][pr*SMS+cn] = uh;
            *(uint4*)&sh[ns][1][pr*SMS+cn] = ul;
            float4 e0, e1;
            e0.x = __expf(b0.x - sm[cn+0]) * sr[cn+0]; e1.x = __expf(b1.x - sm[cn+0]) * sr[cn+0];
            e0.y = __expf(b0.y - sm[cn+1]) * sr[cn+1]; e1.y = __expf(b1.y - sm[cn+1]) * sr[cn+1];
            e0.z = __expf(b0.z - sm[cn+2]) * sr[cn+2]; e1.z = __expf(b1.z - sm[cn+2]) * sr[cn+2];
            e0.w = __expf(b0.w - sm[cn+3]) * sr[cn+3]; e1.w = __expf(b1.w - sm[cn+3]) * sr[cn+3];
            bf_split2(e0.x, e1.x, uh.x, ul.x);
            bf_split2(e0.y, e1.y, uh.y, ul.y);
            bf_split2(e0.z, e1.z, uh.z, ul.z);
            bf_split2(e0.w, e1.w, uh.w, ul.w);
            *(uint4*)&sh[ns][2][pr*SMS+cn] = uh;
            *(uint4*)&sh[ns][3][pr*SMS+cn] = ul;
            __syncthreads();
        }
    }

    // write partials (same proven index pattern as the S store)
    float* P = &g_part[ls][b][0][0];
    #pragma unroll
    for (int mf = 0; mf < 4; mf++) {
        #pragma unroll
        for (int nf = 0; nf < 4; nf++) {
            int r = wm + mf * 16 + gid;           // c index
            int cc = p0 + wn + nf * 8 + 2 * tig;  // p index
            *(float2*)(P + (size_t)r * HW + cc)       = make_float2(acc[mf][nf][0], acc[mf][nf][1]);
            *(float2*)(P + (size_t)(r + 8) * HW + cc) = make_float2(acc[mf][nf][2], acc[mf][nf][3]);
        }
    }
}

// ---------------------------------------------------------------------------
// combine2: sum split-K partials + mask-blend epilogue
// ---------------------------------------------------------------------------
__global__ void combine2(const float* __restrict__ fg,
                         const float* __restrict__ mask,
                         float* __restrict__ out) {
    int idx = blockIdx.x * blockDim.x + threadIdx.x;   // over NB*C*HW
    int p = idx & (HW - 1);
    int b = idx >> 19;                                 // C*HW = 2^19
    int c = (idx >> 12) & (C - 1);
    float v = 0.f;
    #pragma unroll
    for (int s = 0; s < KSPLIT; s++)
        v += g_part[s][b][c][p];
    float mk = mask[b * HW + p];
    out[idx] = v * (1.f - mk) * (1.f / 9.f) + fg[idx] * mk;
}

extern "C" void kernel_launch(void* const* d_in, const int* in_sizes, int n_in,
                              void* d_out, int out_size) {
    const float* fg   = (const float*)d_in[0];
    const float* mask = (const float*)d_in[1];
    float* out = (float*)d_out;

    k_prep<<<dim3(HW, NB), C>>>(fg);
    y_prep<<<(NB * C * HW) / 256, 256>>>(fg);
    gemm1_mma<<<dim3(HW / 128, HW / 128, NB), 256>>>();
    softmax_combine<<<(NB * HW) / 256, 256>>>();
    gemm2_mma<<<dim3(HW / 128, NB, KSPLIT), 256>>>();
    combine2<<<(NB * C * HW) / 256, 256>>>(fg, mask, out);
}

// round 11
// speedup vs baseline: 2.9569x; 1.0001x over previous
#include <cuda_runtime.h>
#include <cuda_bf16.h>
#include <cstdint>

#define NB 4
#define C 128
#define HW 4096
#define EPSF 1e-7f
#define NTILES (HW / 128)
#define SMS 136      // padded shared stride (uint32 units)
#define KSPLIT 4

// ---------------- scratch ----------------
__device__ __align__(128) float g_k [NB][HW][C];    // K[l][c]
__device__ __align__(128) float g_y [NB][C][HW];    // boxsum [c][p]
__device__ __align__(128) float g_S [NB][HW][HW];   // S[l][p]
__device__ __align__(128) float g_part[KSPLIT][NB][C][HW];  // gemm2 split-K partials
__device__ float g_pm[NTILES][NB][HW];
__device__ float g_ps[NTILES][NB][HW];
__device__ float g_cmax[NB][HW];
__device__ float g_crcp[NB][HW];

// ---------------- helpers (proven) ----------------
__device__ __forceinline__ void bf_split2(float v0, float v1, uint32_t& h, uint32_t& l) {
    __nv_bfloat16 h0 = __float2bfloat16(v0);
    __nv_bfloat16 h1 = __float2bfloat16(v1);
    __nv_bfloat16 l0 = __float2bfloat16(v0 - __bfloat162float(h0));
    __nv_bfloat16 l1 = __float2bfloat16(v1 - __bfloat162float(h1));
    h = (uint32_t)__bfloat16_as_ushort(h0) | ((uint32_t)__bfloat16_as_ushort(h1) << 16);
    l = (uint32_t)__bfloat16_as_ushort(l0) | ((uint32_t)__bfloat16_as_ushort(l1) << 16);
}
__device__ __forceinline__ void mma16(float* c, const uint32_t* a, const uint32_t* b) {
    asm volatile("mma.sync.aligned.m16n8k16.row.col.f32.bf16.bf16.f32 "
        "{%0,%1,%2,%3},{%4,%5,%6,%7},{%8,%9},{%0,%1,%2,%3};"
        : "+f"(c[0]), "+f"(c[1]), "+f"(c[2]), "+f"(c[3])
        : "r"(a[0]), "r"(a[1]), "r"(a[2]), "r"(a[3]), "r"(b[0]), "r"(b[1]));
}

// one BK=16 stage of 3-term split-bf16 mma (proven fragment mapping, kk2=0 only)
__device__ __forceinline__ void mma_block(const uint32_t* pAh, const uint32_t* pAl,
                                          const uint32_t* pBh, const uint32_t* pBl,
                                          int wm, int wn, int gid, int tig,
                                          float acc[4][4][4]) {
    uint32_t ah[4][4], al[4][4], bh[4][2], bl[4][2];
    #pragma unroll
    for (int mf = 0; mf < 4; mf++) {
        int m = wm + mf * 16 + gid;
        ah[mf][0] = pAh[tig * SMS + m];
        ah[mf][1] = pAh[tig * SMS + m + 8];
        ah[mf][2] = pAh[(tig + 4) * SMS + m];
        ah[mf][3] = pAh[(tig + 4) * SMS + m + 8];
        al[mf][0] = pAl[tig * SMS + m];
        al[mf][1] = pAl[tig * SMS + m + 8];
        al[mf][2] = pAl[(tig + 4) * SMS + m];
        al[mf][3] = pAl[(tig + 4) * SMS + m + 8];
    }
    #pragma unroll
    for (int nf = 0; nf < 4; nf++) {
        int n = wn + nf * 8 + gid;
        bh[nf][0] = pBh[tig * SMS + n];
        bh[nf][1] = pBh[(tig + 4) * SMS + n];
        bl[nf][0] = pBl[tig * SMS + n];
        bl[nf][1] = pBl[(tig + 4) * SMS + n];
    }
    #pragma unroll
    for (int mf = 0; mf < 4; mf++)
        #pragma unroll
        for (int nf = 0; nf < 4; nf++) {
            mma16(acc[mf][nf], ah[mf], bl[nf]);
            mma16(acc[mf][nf], al[mf], bh[nf]);
            mma16(acc[mf][nf], ah[mf], bh[nf]);
        }
}

// ---------------------------------------------------------------------------
// prep (proven)
// ---------------------------------------------------------------------------
__global__ void k_prep(const float* __restrict__ fg) {
    int l = blockIdx.x, b = blockIdx.y, c = threadIdx.x;
    float v = fg[((b * C + c) * HW) + l] + EPSF;
    float s = v * v;
    #pragma unroll
    for (int o = 16; o > 0; o >>= 1) s += __shfl_xor_sync(0xffffffffu, s, o);
    __shared__ float ws[4];
    if ((c & 31) == 0) ws[c >> 5] = s;
    __syncthreads();
    float tot = ws[0] + ws[1] + ws[2] + ws[3];
    g_k[b][l][c] = v * rsqrtf(tot);
}

__global__ void y_prep(const float* __restrict__ fg) {
    int idx = blockIdx.x * blockDim.x + threadIdx.x;
    int p = idx & (HW - 1);
    int bc = idx >> 12;
    int i = p >> 6, j = p & 63;
    const float* base = fg + (size_t)bc * HW;
    float s = 0.f;
    #pragma unroll
    for (int di = -1; di <= 1; di++) {
        int ii = i + di;
        if (ii < 0 || ii >= 64) continue;
        #pragma unroll
        for (int dj = -1; dj <= 1; dj++) {
            int jj = j + dj;
            if (jj < 0 || jj >= 64) continue;
            s += base[ii * 64 + jj];
        }
    }
    ((float*)g_y)[idx] = s;
}

// ---------------------------------------------------------------------------
// gemm1: S[l][p] = K[l][:] . Y[:,p]  + partial stats
// double-buffered BK=16, 8 chunks, one sync per chunk
// ---------------------------------------------------------------------------
__global__ __launch_bounds__(256) void gemm1_mma() {
    __shared__ uint32_t sh[2][4][8 * SMS];   // [stage][Ah,Al,Bh,Bl][k2*SMS+col]
    __shared__ float pm_sh[2][128], ps_sh[2][128];

    int b = blockIdx.z, lt = blockIdx.y;
    int l0 = lt * 128, p0 = blockIdx.x * 128;
    int tid = threadIdx.x, wid = tid >> 5, lane = tid & 31;
    int gid = lane >> 2, tig = lane & 3;
    int wm = (wid & 1) * 64, wn = (wid >> 1) * 32;

    const float* Ag = &g_k[b][l0][0];   // rows = m (l), cols = k (c)
    const float* Bg = &g_y[b][0][p0];   // rows = k (c), cols = n (p)

    int am = tid & 127, ah4 = (tid >> 7) * 4;   // A: row am, pairs [ah4, ah4+4)
    int pr = tid >> 5,  bn = (tid & 31) * 4;    // B: pair-row pr, n [bn, bn+4)

    float4 a0, a1, b0, b1;
    a0 = *(const float4*)(Ag + am * C + ah4 * 2);
    a1 = *(const float4*)(Ag + am * C + ah4 * 2 + 4);
    b0 = *(const float4*)(Bg + (size_t)(2 * pr) * HW + bn);
    b1 = *(const float4*)(Bg + (size_t)(2 * pr + 1) * HW + bn);
    {
        uint32_t h, l;
        bf_split2(a0.x, a0.y, h, l); sh[0][0][(ah4+0)*SMS+am] = h; sh[0][1][(ah4+0)*SMS+am] = l;
        bf_split2(a0.z, a0.w, h, l); sh[0][0][(ah4+1)*SMS+am] = h; sh[0][1][(ah4+1)*SMS+am] = l;
        bf_split2(a1.x, a1.y, h, l); sh[0][0][(ah4+2)*SMS+am] = h; sh[0][1][(ah4+2)*SMS+am] = l;
        bf_split2(a1.z, a1.w, h, l); sh[0][0][(ah4+3)*SMS+am] = h; sh[0][1][(ah4+3)*SMS+am] = l;
        uint4 uh, ul;
        bf_split2(b0.x, b1.x, uh.x, ul.x);
        bf_split2(b0.y, b1.y, uh.y, ul.y);
        bf_split2(b0.z, b1.z, uh.z, ul.z);
        bf_split2(b0.w, b1.w, uh.w, ul.w);
        *(uint4*)&sh[0][2][pr*SMS+bn] = uh;
        *(uint4*)&sh[0][3][pr*SMS+bn] = ul;
    }
    __syncthreads();

    float acc[4][4][4] = {};
    for (int it = 0; it < 8; it++) {
        int st = it & 1;
        if (it < 7) {
            int c0 = (it + 1) * 16;
            a0 = *(const float4*)(Ag + am * C + c0 + ah4 * 2);
            a1 = *(const float4*)(Ag + am * C + c0 + ah4 * 2 + 4);
            b0 = *(const float4*)(Bg + (size_t)(c0 + 2 * pr) * HW + bn);
            b1 = *(const float4*)(Bg + (size_t)(c0 + 2 * pr + 1) * HW + bn);
        }
        mma_block(sh[st][0], sh[st][1], sh[st][2], sh[st][3], wm, wn, gid, tig, acc);
        if (it < 7) {
            int ns = st ^ 1;
            uint32_t h, l;
            bf_split2(a0.x, a0.y, h, l); sh[ns][0][(ah4+0)*SMS+am] = h; sh[ns][1][(ah4+0)*SMS+am] = l;
            bf_split2(a0.z, a0.w, h, l); sh[ns][0][(ah4+1)*SMS+am] = h; sh[ns][1][(ah4+1)*SMS+am] = l;
            bf_split2(a1.x, a1.y, h, l); sh[ns][0][(ah4+2)*SMS+am] = h; sh[ns][1][(ah4+2)*SMS+am] = l;
            bf_split2(a1.z, a1.w, h, l); sh[ns][0][(ah4+3)*SMS+am] = h; sh[ns][1][(ah4+3)*SMS+am] = l;
            uint4 uh, ul;
            bf_split2(b0.x, b1.x, uh.x, ul.x);
            bf_split2(b0.y, b1.y, uh.y, ul.y);
            bf_split2(b0.z, b1.z, uh.z, ul.z);
            bf_split2(b0.w, b1.w, uh.w, ul.w);
            *(uint4*)&sh[ns][2][pr*SMS+bn] = uh;
            *(uint4*)&sh[ns][3][pr*SMS+bn] = ul;
            __syncthreads();
        }
    }

    // ---- partial softmax stats (proven) ----
    #pragma unroll
    for (int nf = 0; nf < 4; nf++) {
        #pragma unroll
        for (int h = 0; h < 2; h++) {
            float mx = -1e30f;
            #pragma unroll
            for (int mf = 0; mf < 4; mf++)
                mx = fmaxf(mx, fmaxf(acc[mf][nf][h], acc[mf][nf][2 + h]));
            float sum = 0.f;
            #pragma unroll
            for (int mf = 0; mf < 4; mf++)
                sum += __expf(acc[mf][nf][h] - mx) + __expf(acc[mf][nf][2 + h] - mx);
            #pragma unroll
            for (int off = 4; off < 32; off <<= 1) {
                float mo = __shfl_xor_sync(0xffffffffu, mx, off);
                float so = __shfl_xor_sync(0xffffffffu, sum, off);
                float mn = fmaxf(mx, mo);
                sum = sum * __expf(mx - mn) + so * __expf(mo - mn);
                mx = mn;
            }
            if (gid == 0) {
                int col = wn + nf * 8 + 2 * tig + h;
                pm_sh[wid & 1][col] = mx;
                ps_sh[wid & 1][col] = sum;
            }
        }
    }
    __syncthreads();
    if (tid < 128) {
        float m0 = pm_sh[0][tid], m1 = pm_sh[1][tid];
        float mn = fmaxf(m0, m1);
        float s = ps_sh[0][tid] * __expf(m0 - mn) + ps_sh[1][tid] * __expf(m1 - mn);
        g_pm[lt][b][p0 + tid] = mn;
        g_ps[lt][b][p0 + tid] = s;
    }

    // ---- store S tile (proven) ----
    #pragma unroll
    for (int mf = 0; mf < 4; mf++) {
        #pragma unroll
        for (int nf = 0; nf < 4; nf++) {
            int r = l0 + wm + mf * 16 + gid;
            int cc = p0 + wn + nf * 8 + 2 * tig;
            *(float2*)&g_S[b][r][cc]     = make_float2(acc[mf][nf][0], acc[mf][nf][1]);
            *(float2*)&g_S[b][r + 8][cc] = make_float2(acc[mf][nf][2], acc[mf][nf][3]);
        }
    }
}

// ---------------------------------------------------------------------------
// combine (proven)
// ---------------------------------------------------------------------------
__global__ void softmax_combine() {
    int idx = blockIdx.x * blockDim.x + threadIdx.x;
    int b = idx >> 12;
    int p = idx & (HW - 1);
    float m = g_pm[0][b][p];
    float s = g_ps[0][b][p];
    #pragma unroll
    for (int t = 1; t < NTILES; t++) {
        float mt = g_pm[t][b][p];
        float st = g_ps[t][b][p];
        float mn = fmaxf(m, mt);
        s = s * __expf(m - mn) + st * __expf(mt - mn);
        m = mn;
    }
    g_cmax[b][p] = m;
    g_crcp[b][p] = 1.f / s;
}

// ---------------------------------------------------------------------------
// gemm2 (split-K x4): g_part[ls][b][c][p] = sum_{l in split} K[l][c]*softmax(S)[l][p]
// double-buffered BK=16, 64 chunks per split, one sync per chunk
// ---------------------------------------------------------------------------
__global__ __launch_bounds__(256) void gemm2_mma() {
    __shared__ uint32_t sh[2][4][8 * SMS];
    __shared__ float sm[128], sr[128];

    int b = blockIdx.y, p0 = blockIdx.x * 128, ls = blockIdx.z;
    int lbase = ls * (HW / KSPLIT);
    int tid = threadIdx.x, wid = tid >> 5, lane = tid & 31;
    int gid = lane >> 2, tig = lane & 3;
    int wm = (wid & 1) * 64, wn = (wid >> 1) * 32;

    if (tid < 128) {
        sm[tid] = g_cmax[b][p0 + tid];
        sr[tid] = g_crcp[b][p0 + tid];
    }
    __syncthreads();

    const float* Kg = &g_k[b][0][0];   // rows = l, cols = c
    const float* Sg = &g_S[b][0][0];   // rows = l, cols = p

    int pr = tid >> 5, cn = (tid & 31) * 4;

    float4 a0, a1, b0, b1;
    a0 = *(const float4*)(Kg + (size_t)(lbase + 2 * pr)     * C + cn);
    a1 = *(const float4*)(Kg + (size_t)(lbase + 2 * pr + 1) * C + cn);
    b0 = *(const float4*)(Sg + (size_t)(lbase + 2 * pr)     * HW + p0 + cn);
    b1 = *(const float4*)(Sg + (size_t)(lbase + 2 * pr + 1) * HW + p0 + cn);
    {
        uint4 uh, ul;
        bf_split2(a0.x, a1.x, uh.x, ul.x);
        bf_split2(a0.y, a1.y, uh.y, ul.y);
        bf_split2(a0.z, a1.z, uh.z, ul.z);
        bf_split2(a0.w, a1.w, uh.w, ul.w);
        *(uint4*)&sh[0][0][pr*SMS+cn] = uh;
        *(uint4*)&sh[0][1][pr*SMS+cn] = ul;
        float4 e0, e1;
        e0.x = __expf(b0.x - sm[cn+0]) * sr[cn+0]; e1.x = __expf(b1.x - sm[cn+0]) * sr[cn+0];
        e0.y = __expf(b0.y - sm[cn+1]) * sr[cn+1]; e1.y = __expf(b1.y - sm[cn+1]) * sr[cn+1];
        e0.z = __expf(b0.z - sm[cn+2]) * sr[cn+2]; e1.z = __expf(b1.z - sm[cn+2]) * sr[cn+2];
        e0.w = __expf(b0.w - sm[cn+3]) * sr[cn+3]; e1.w = __expf(b1.w - sm[cn+3]) * sr[cn+3];
        bf_split2(e0.x, e1.x, uh.x, ul.x);
        bf_split2(e0.y, e1.y, uh.y, ul.y);
        bf_split2(e0.z, e1.z, uh.z, ul.z);
        bf_split2(e0.w, e1.w, uh.w, ul.w);
        *(uint4*)&sh[0][2][pr*SMS+cn] = uh;
        *(uint4*)&sh[0][3][pr*SMS+cn] = ul;
    }
    __syncthreads();

    float acc[4][4][4] = {};
    const int NIT = (HW / KSPLIT) / 16;   // 64
    for (int it = 0; it < NIT; it++) {
        int st = it & 1;
        if (it < NIT - 1) {
            int l0 = lbase + (it + 1) * 16;
            a0 = *(const float4*)(Kg + (size_t)(l0 + 2 * pr)     * C + cn);
            a1 = *(const float4*)(Kg + (size_t)(l0 + 2 * pr + 1) * C + cn);
            b0 = *(const float4*)(Sg + (size_t)(l0 + 2 * pr)     * HW + p0 + cn);
            b1 = *(const float4*)(Sg + (size_t)(l0 + 2 * pr + 1) * HW + p0 + cn);
        }
        mma_block(sh[st][0], sh[st][1], sh[st][2], sh[st][3], wm, wn, gid, tig, acc);
        if (it < NIT - 1) {
            int ns = st ^ 1;
            uint4 uh, ul;
            bf_split2(a0.x, a1.x, uh.x, ul.x);
            bf_split2(a0.y, a1.y, uh.y, ul.y);
            bf_split2(a0.z, a1.z, uh.z, ul.z);
            bf_split2(a0.w, a1.w, uh.w, ul.w);
            *(uint4*)&sh[ns][0][pr*SMS+cn] = uh;
            *(uint4*)&sh[ns][1][pr*SMS+cn] = ul;
            float4 e0, e1;
            e0.x = __expf(b0.x - sm[cn+0]) * sr[cn+0]; e1.x = __expf(b1.x - sm[cn+0]) * sr[cn+0];
            e0.y = __expf(b0.y - sm[cn+1]) * sr[cn+1]; e1.y = __expf(b1.y - sm[cn+1]) * sr[cn+1];
            e0.z = __expf(b0.z - sm[cn+2]) * sr[cn+2]; e1.z = __expf(b1.z - sm[cn+2]) * sr[cn+2];
            e0.w = __expf(b0.w - sm[cn+3]) * sr[cn+3]; e1.w = __expf(b1.w - sm[cn+3]) * sr[cn+3];
            bf_split2(e0.x, e1.x, uh.x, ul.x);
            bf_split2(e0.y, e1.y, uh.y, ul.y);
            bf_split2(e0.z, e1.z, uh.z, ul.z);
            bf_split2(e0.w, e1.w, uh.w, ul.w);
            *(uint4*)&sh[ns][2][pr*SMS+cn] = uh;
            *(uint4*)&sh[ns][3][pr*SMS+cn] = ul;
            __syncthreads();
        }
    }

    // write partials (same proven index pattern as the S store)
    float* P = &g_part[ls][b][0][0];
    #pragma unroll
    for (int mf = 0; mf < 4; mf++) {
        #pragma unroll
        for (int nf = 0; nf < 4; nf++) {
            int r = wm + mf * 16 + gid;           // c index
            int cc = p0 + wn + nf * 8 + 2 * tig;  // p index
            *(float2*)(P + (size_t)r * HW + cc)       = make_float2(acc[mf][nf][0], acc[mf][nf][1]);
            *(float2*)(P + (size_t)(r + 8) * HW + cc) = make_float2(acc[mf][nf][2], acc[mf][nf][3]);
        }
    }
}

// ---------------------------------------------------------------------------
// combine2: sum split-K partials + mask-blend epilogue
// ---------------------------------------------------------------------------
__global__ void combine2(const float* __restrict__ fg,
                         const float* __restrict__ mask,
                         float* __restrict__ out) {
    int idx = blockIdx.x * blockDim.x + threadIdx.x;   // over NB*C*HW
    int p = idx & (HW - 1);
    int b = idx >> 19;                                 // C*HW = 2^19
    int c = (idx >> 12) & (C - 1);
    float v = 0.f;
    #pragma unroll
    for (int s = 0; s < KSPLIT; s++)
        v += g_part[s][b][c][p];
    float mk = mask[b * HW + p];
    out[idx] = v * (1.f - mk) * (1.f / 9.f) + fg[idx] * mk;
}

extern "C" void kernel_launch(void* const* d_in, const int* in_sizes, int n_in,
                              void* d_out, int out_size) {
    const float* fg   = (const float*)d_in[0];
    const float* mask = (const float*)d_in[1];
    float* out = (float*)d_out;

    k_prep<<<dim3(HW, NB), C>>>(fg);
    y_prep<<<(NB * C * HW) / 256, 256>>>(fg);
    gemm1_mma<<<dim3(HW / 128, HW / 128, NB), 256>>>();
    softmax_combine<<<(NB * HW) / 256, 256>>>();
    gemm2_mma<<<dim3(HW / 128, NB, KSPLIT), 256>>>();
    combine2<<<(NB * C * HW) / 256, 256>>>(fg, mask, out);
}